// round 15
// baseline (speedup 1.0000x reference)
#include <cuda_runtime.h>
#include <cuda_fp16.h>
#include <cstdint>
#include <math.h>

// Problem constants
#define BQ 2
#define NSEQ 2048
#define VV 32000
#define DD 1024
#define NLAY 4
#define NF 1025          // NSEQ/2 + 1

#define MPAD 4224

// MMA tiling: CTA 128x128, BK=64, warp tile 64x64 (2x2 warps, 128 threads)
#define ROWH 72                   // padded row stride in halves (144 B)
#define STGH (128 * ROWH)
#define NSTG 3
#define SMEM_DYN (NSTG * 2 * STGH * 2)   // 110592 B

// ---------------------------------------------------------------------------
// Scratch. A stored as [M, 2K] fp16 (hi | lo). W stored as [N, K] fp16 hi only.
// Interior GEMMs run virtual K2=2K (Ah*Wh + Al*Wh). Head runs Kv=K (hi only).
// ---------------------------------------------------------------------------
__device__ float g_x [BQ * NSEQ * DD];
__device__ float g_y [BQ * NSEQ * DD];
__device__ float g_go[2 * BQ * NF * DD];                  // freq-MLP out re | im
__device__ float2 g_tw[NSEQ / 2];

__device__ __half g_ab1[(size_t)MPAD * 2 * DD];           // split A', K=1024 inputs
__device__ __half g_ab2[(size_t)MPAD * 2 * 4096];         // split A', wide K (<=4096)
__device__ __half g_wt [(size_t)VV * DD];                 // W' hi (N<=32000, K=1024)
__device__ __half g_wt2[(size_t)DD * 4096];               // W' hi (N=1024, K<=4096)

// ---------------------------------------------------------------------------
// Helpers
// ---------------------------------------------------------------------------
__device__ __forceinline__ uint32_t cvta_smem(const void* p) {
    uint32_t a;
    asm("{ .reg .u64 t; cvta.to.shared.u64 t, %1; cvt.u32.u64 %0, t; }" : "=r"(a) : "l"(p));
    return a;
}
__device__ __forceinline__ void cp16(uint32_t dst, const void* src) {
    asm volatile("cp.async.cg.shared.global [%0], [%1], 16;" :: "r"(dst), "l"(src));
}
__device__ __forceinline__ void ldm_x4(uint32_t* r, uint32_t addr) {
    asm volatile("ldmatrix.sync.aligned.m8n8.x4.shared.b16 {%0,%1,%2,%3}, [%4];"
                 : "=r"(r[0]), "=r"(r[1]), "=r"(r[2]), "=r"(r[3]) : "r"(addr));
}
__device__ __forceinline__ void mma_fp16(float* c, const uint32_t* a, const uint32_t* b) {
    asm volatile(
        "mma.sync.aligned.m16n8k16.row.col.f32.f16.f16.f32 "
        "{%0,%1,%2,%3}, {%4,%5,%6,%7}, {%8,%9}, {%0,%1,%2,%3};"
        : "+f"(c[0]), "+f"(c[1]), "+f"(c[2]), "+f"(c[3])
        : "r"(a[0]), "r"(a[1]), "r"(a[2]), "r"(a[3]), "r"(b[0]), "r"(b[1]));
}

// split-store a pair of adjacent values: hi at +0, lo at +K (fp16)
__device__ __forceinline__ void split_store2(__half* p, int K, float a, float b) {
    __half ha = __float2half_rn(a), hb = __float2half_rn(b);
    __half la = __float2half_rn(a - __half2float(ha));
    __half lb = __float2half_rn(b - __half2float(hb));
    __half2 hh; hh.x = ha; hh.y = hb;
    __half2 ll; ll.x = la; ll.y = lb;
    *(__half2*)(p)     = hh;
    *(__half2*)(p + K) = ll;
}

__device__ __forceinline__ float gelu_exact(float v) {
    return 0.5f * v * (1.0f + erff(v * 0.70710678118654752f));
}

// ---------------------------------------------------------------------------
// Twiddles / embed
// ---------------------------------------------------------------------------
__global__ void twiddle_kernel() {
    int k = threadIdx.x;
    double ang = -2.0 * 3.14159265358979323846 * (double)k / (double)NSEQ;
    g_tw[k] = make_float2((float)cos(ang), (float)sin(ang));
}

__global__ void embed_kernel(const int* __restrict__ ids,
                             const float* __restrict__ emb,
                             const float* __restrict__ pos) {
    int t = blockIdx.x * blockDim.x + threadIdx.x;
    int bn = t >> 8;
    int d4 = (t & 255) << 2;
    int id = ids[bn];
    int n  = bn & (NSEQ - 1);
    float4 e = *(const float4*)(emb + (size_t)id * DD + d4);
    float4 p = *(const float4*)(pos + (size_t)n  * DD + d4);
    *(float4*)(g_x + (size_t)bn * DD + d4) =
        make_float4(e.x + p.x, e.y + p.y, e.z + p.z, e.w + p.w);
}

// ---------------------------------------------------------------------------
// FFT core
// ---------------------------------------------------------------------------
__device__ __forceinline__ int bitrev11(int i) { return (int)(__brev((unsigned)i) >> 21); }

template <bool INV>
__device__ __forceinline__ void fft_stages(float2* s, int tid) {
    int hbits = 0;
    for (int len = 2; len <= NSEQ; len <<= 1, hbits++) {
        int half = len >> 1;
        int step = NSEQ >> (hbits + 1);
        for (int t = tid; t < NSEQ / 2; t += 256) {
            int j   = t & (half - 1);
            int idx = ((t >> hbits) << (hbits + 1)) + j;
            float2 w = g_tw[j * step];
            if (INV) w.y = -w.y;
            float2 u = s[idx];
            float2 v = s[idx + half];
            float vwx = v.x * w.x - v.y * w.y;
            float vwy = v.x * w.y + v.y * w.x;
            s[idx]        = make_float2(u.x + vwx, u.y + vwy);
            s[idx + half] = make_float2(u.x - vwx, u.y - vwy);
        }
        __syncthreads();
    }
}

// Forward: two real channels per complex FFT; writes split A' (row stride 2*DD)
__global__ void rfft2_kernel(__half* __restrict__ Os) {
    __shared__ float2 s[NSEQ];
    int tid = threadIdx.x;
    int b   = blockIdx.x >> 9;
    int d0  = (blockIdx.x & 511) << 1;
    const float* x0 = g_x + (size_t)b * NSEQ * DD + d0;
    for (int i = tid; i < NSEQ; i += 256)
        s[bitrev11(i)] = *(const float2*)(x0 + (size_t)i * DD);
    __syncthreads();
    fft_stages<false>(s, tid);
    for (int k = tid; k < NF; k += 256) {
        float2 Z1 = s[k];
        float2 Z2 = s[(NSEQ - k) & (NSEQ - 1)];
        float re1 = 0.5f * (Z1.x + Z2.x), im1 = 0.5f * (Z1.y - Z2.y);
        float re2 = 0.5f * (Z1.y + Z2.y), im2 = 0.5f * (Z2.x - Z1.x);
        split_store2(Os + (size_t)(b * NF + k) * (2 * DD) + d0, DD, re1, re2);
        split_store2(Os + (size_t)((BQ + b) * NF + k) * (2 * DD) + d0, DD, im1, im2);
    }
}

// Inverse: two spectra from g_go -> one complex iFFT -> g_y
__global__ void irfft2_kernel() {
    __shared__ float2 s[NSEQ];
    __shared__ float2 G1[NF];
    __shared__ float2 G2[NF];
    int tid = threadIdx.x;
    int b   = blockIdx.x >> 9;
    int d0  = (blockIdx.x & 511) << 1;
    for (int k = tid; k < NF; k += 256) {
        float2 re = *(const float2*)(g_go + (size_t)(b * NF + k) * DD + d0);
        float2 im = *(const float2*)(g_go + (size_t)((BQ + b) * NF + k) * DD + d0);
        G1[k] = make_float2(re.x, im.x);
        G2[k] = make_float2(re.y, im.y);
    }
    __syncthreads();
    for (int i = tid; i < NSEQ; i += 256) {
        float2 z;
        if (i <= NSEQ / 2) {
            float2 a = G1[i], c = G2[i];
            z = make_float2(a.x - c.y, a.y + c.x);
        } else {
            float2 a = G1[NSEQ - i], c = G2[NSEQ - i];
            z = make_float2(a.x + c.y, c.x - a.y);
        }
        s[bitrev11(i)] = z;
    }
    __syncthreads();
    fft_stages<true>(s, tid);
    float* out = g_y + (size_t)b * NSEQ * DD + d0;
    const float inv = 1.0f / (float)NSEQ;
    for (int i = tid; i < NSEQ; i += 256)
        *(float2*)(out + (size_t)i * DD) = make_float2(s[i].x * inv, s[i].y * inv);
}

// ---------------------------------------------------------------------------
// Weight conversion: W [K,N] fp32 -> W' [N,K] fp16 hi only
// ---------------------------------------------------------------------------
__global__ void convW_kernel(const float* __restrict__ W,
                             __half* __restrict__ O, int K, int N) {
    __shared__ float t[32][33];
    int n0 = blockIdx.x * 32, k0 = blockIdx.y * 32;
    int tx = threadIdx.x & 31, tr = threadIdx.x >> 5;
    for (int r = tr; r < 32; r += 8)
        t[r][tx] = W[(size_t)(k0 + r) * N + n0 + tx];
    __syncthreads();
    for (int r = tr; r < 32; r += 8) {
        float v = t[tx][r];
        O[(size_t)(n0 + r) * K + k0 + tx] = __float2half_rn(v);
    }
}

// ---------------------------------------------------------------------------
// HMMA GEMM over virtual Kv: A row stride Ka elements; W [N,Kw] wraps at Kw.
// Interior: Ka=2K, Kw=K, Kv=2K (Ah*Wh + Al*Wh). Head: Kv=K (hi only).
// CTA 128x128, BK=64, 3-stage cp.async, 128 threads, warp tile 64x64 (2x2).
// mode 0: fp32 out; mode 1: split out.
// ---------------------------------------------------------------------------
__global__ void __launch_bounds__(128, 2)
mma_kernel(const __half* __restrict__ Abf,
           const __half* __restrict__ Wt,
           const float* __restrict__ bias,
           float* __restrict__ C,
           __half* __restrict__ Cs,
           int M, int Nn, int Ka, int Kw, int Kv, int act, int mode) {
    extern __shared__ __half sm[];
    uint32_t smBase = cvta_smem(sm);

    int tid  = threadIdx.x;
    int bm   = blockIdx.x * 128;
    int bn   = blockIdx.y * 128;
    int wid  = tid >> 5, lane = tid & 31;
    int wm   = (wid >> 1) * 64;        // 0 or 64
    int wn   = (wid & 1) * 64;         // 0 or 64

    float c[4][8][4];
#pragma unroll
    for (int i = 0; i < 4; i++)
#pragma unroll
        for (int j = 0; j < 8; j++) {
            c[i][j][0] = 0.f; c[i][j][1] = 0.f; c[i][j][2] = 0.f; c[i][j][3] = 0.f;
        }

#define A_OFF(stg) (smBase + (uint32_t)(stg) * (2 * STGH * 2))
#define B_OFF(stg) (A_OFF(stg) + STGH * 2)

    // Per stage: A 128 rows x 8 chunks(16B) + B 128 rows x 8 chunks = 2048 chunks,
    // 16 per thread (128 threads).
#define LOAD_STAGE(stg, kt)                                                           \
    do {                                                                              \
        int k_  = (kt) << 6;                                                          \
        int kw_ = (k_ < Kw) ? k_ : k_ - Kw;                                           \
        _Pragma("unroll")                                                             \
        for (int i_ = 0; i_ < 16; i_++) {                                             \
            int ch_ = tid + (i_ << 7);                                                \
            if (ch_ < 1024) {                                                         \
                int row_ = ch_ >> 3, cc_ = (ch_ & 7) << 3;                            \
                cp16(A_OFF(stg) + (uint32_t)(row_ * ROWH + cc_) * 2,                  \
                     Abf + (size_t)(bm + row_) * Ka + k_ + cc_);                      \
            } else {                                                                  \
                int bh_ = ch_ - 1024;                                                 \
                int row_ = bh_ >> 3, cc_ = (bh_ & 7) << 3;                            \
                cp16(B_OFF(stg) + (uint32_t)(row_ * ROWH + cc_) * 2,                  \
                     Wt + (size_t)(bn + row_) * Kw + kw_ + cc_);                      \
            }                                                                         \
        }                                                                             \
    } while (0)

    int T = Kv >> 6;

#pragma unroll
    for (int p = 0; p < NSTG - 1; p++) {
        LOAD_STAGE(p, p);
        asm volatile("cp.async.commit_group;" ::: "memory");
    }

    for (int t = 0; t < T; t++) {
        asm volatile("cp.async.wait_group %0;" :: "n"(NSTG - 2) : "memory");
        __syncthreads();

        if (t + NSTG - 1 < T) {
            int st = (t + NSTG - 1) % NSTG;
            LOAD_STAGE(st, t + NSTG - 1);
        }
        asm volatile("cp.async.commit_group;" ::: "memory");

        int st = t % NSTG;
        uint32_t aB = A_OFF(st), bB = B_OFF(st);
#pragma unroll
        for (int ks = 0; ks < 4; ks++) {
            uint32_t a[4][4];
#pragma unroll
            for (int mt = 0; mt < 4; mt++) {
                int row = wm + mt * 16 + ((lane >> 3) & 1) * 8 + (lane & 7);
                int col = ks * 16 + (lane >> 4) * 8;
                ldm_x4(a[mt], aB + (uint32_t)(row * ROWH + col) * 2);
            }
            uint32_t b[8][2];
#pragma unroll
            for (int np = 0; np < 4; np++) {
                int nrow = wn + np * 16 + (lane >> 4) * 8 + (lane & 7);
                int col  = ks * 16 + ((lane >> 3) & 1) * 8;
                uint32_t r[4];
                ldm_x4(r, bB + (uint32_t)(nrow * ROWH + col) * 2);
                b[np * 2][0]     = r[0]; b[np * 2][1]     = r[1];
                b[np * 2 + 1][0] = r[2]; b[np * 2 + 1][1] = r[3];
            }
#pragma unroll
            for (int mt = 0; mt < 4; mt++)
#pragma unroll
                for (int nt = 0; nt < 8; nt++)
                    mma_fp16(c[mt][nt], a[mt], b[nt]);
        }
    }

    // epilogue
#pragma unroll
    for (int mt = 0; mt < 4; mt++) {
        int rowa = bm + wm + mt * 16 + (lane >> 2);
        int rowb = rowa + 8;
#pragma unroll
        for (int nt = 0; nt < 8; nt++) {
            int col = bn + wn + nt * 8 + (lane & 3) * 2;
            float b0 = bias[col], b1 = bias[col + 1];
            float v0 = c[mt][nt][0] + b0, v1 = c[mt][nt][1] + b1;
            float v2 = c[mt][nt][2] + b0, v3 = c[mt][nt][3] + b1;
            if (act) {
                v0 = gelu_exact(v0); v1 = gelu_exact(v1);
                v2 = gelu_exact(v2); v3 = gelu_exact(v3);
            }
            if (mode == 0) {
                if (rowa < M) *(float2*)(C + (size_t)rowa * Nn + col) = make_float2(v0, v1);
                if (rowb < M) *(float2*)(C + (size_t)rowb * Nn + col) = make_float2(v2, v3);
            } else {
                if (rowa < M) split_store2(Cs + (size_t)rowa * 2 * Nn + col, Nn, v0, v1);
                if (rowb < M) split_store2(Cs + (size_t)rowb * 2 * Nn + col, Nn, v2, v3);
            }
        }
    }
#undef A_OFF
#undef B_OFF
#undef LOAD_STAGE
}

// ---------------------------------------------------------------------------
// Fused residual add + LayerNorm; writes fp32 x and split fp16 x' (stride 2*DD)
// ---------------------------------------------------------------------------
__global__ void resid_ln_kernel(float* __restrict__ x,
                                const float* __restrict__ y,
                                const float* __restrict__ g,
                                const float* __restrict__ be,
                                __half* __restrict__ xs) {
    __shared__ float red[256];
    int tid = threadIdx.x;
    size_t base = (size_t)blockIdx.x * DD;

    float v[4];
#pragma unroll
    for (int i = 0; i < 4; i++) {
        int d = tid + i * 256;
        v[i] = x[base + d] + y[base + d];
    }
    float s = v[0] + v[1] + v[2] + v[3];
    red[tid] = s;
    __syncthreads();
    for (int o = 128; o > 0; o >>= 1) {
        if (tid < o) red[tid] += red[tid + o];
        __syncthreads();
    }
    float mean = red[0] * (1.0f / DD);
    __syncthreads();

    float sq = 0.0f;
#pragma unroll
    for (int i = 0; i < 4; i++) { float t = v[i] - mean; sq += t * t; }
    red[tid] = sq;
    __syncthreads();
    for (int o = 128; o > 0; o >>= 1) {
        if (tid < o) red[tid] += red[tid + o];
        __syncthreads();
    }
    float var = red[0] * (1.0f / DD);
    float r = rsqrtf(var + 1e-5f);

    __half* xrow = xs + (size_t)blockIdx.x * 2 * DD;
#pragma unroll
    for (int i = 0; i < 4; i++) {
        int d = tid + i * 256;
        float o = (v[i] - mean) * r * g[d] + be[d];
        x[base + d] = o;
        __half h = __float2half_rn(o);
        __half l = __float2half_rn(o - __half2float(h));
        xrow[d]      = h;
        xrow[d + DD] = l;
    }
}

// ---------------------------------------------------------------------------
// Launcher
// ---------------------------------------------------------------------------
static float* sym(const void* s) {
    void* p = nullptr;
    cudaGetSymbolAddress(&p, s);
    return (float*)p;
}

static void conv_w(const float* W, __half* wt, int K, int N) {
    convW_kernel<<<dim3(N / 32, K / 32), 256>>>(W, wt, K, N);
}

// terms: 2 = Ah*Wh + Al*Wh ; 1 = Ah*Wh only (head)
static void run_mma(const __half* Abf, const __half* wt, const float* bias,
                    float* C, __half* Cs, int M, int K, int N, int act, int mode,
                    int terms) {
    mma_kernel<<<dim3((M + 127) / 128, N / 128), 128, SMEM_DYN>>>(
        Abf, wt, bias, C, Cs, M, N, 2 * K, K, terms * K, act, mode);
}

extern "C" void kernel_launch(void* const* d_in, const int* in_sizes, int n_in,
                              void* d_out, int out_size) {
    const int*   ids  = (const int*)  d_in[0];
    const float* emb  = (const float*)d_in[1];
    const float* pos  = (const float*)d_in[2];
    const float* W1f  = (const float*)d_in[3];
    const float* b1f  = (const float*)d_in[4];
    const float* W2f  = (const float*)d_in[5];
    const float* b2f  = (const float*)d_in[6];
    const float* g1   = (const float*)d_in[7];
    const float* be1  = (const float*)d_in[8];
    const float* Wf1  = (const float*)d_in[9];
    const float* bf1  = (const float*)d_in[10];
    const float* Wf2  = (const float*)d_in[11];
    const float* bf2  = (const float*)d_in[12];
    const float* g2   = (const float*)d_in[13];
    const float* be2  = (const float*)d_in[14];
    const float* Wh   = (const float*)d_in[15];
    const float* bh   = (const float*)d_in[16];

    float* x  = sym(g_x);
    float* y  = sym(g_y);
    float* go = sym(g_go);
    __half* ab1 = (__half*)sym(g_ab1);
    __half* ab2 = (__half*)sym(g_ab2);
    __half* wt  = (__half*)sym(g_wt);
    __half* wt2 = (__half*)sym(g_wt2);

    cudaFuncSetAttribute(mma_kernel, cudaFuncAttributeMaxDynamicSharedMemorySize, SMEM_DYN);

    twiddle_kernel<<<1, 1024>>>();
    embed_kernel<<<(BQ * NSEQ * DD / 4) / 256, 256>>>(ids, emb, pos);

    const int MFREQ = 2 * BQ * NF;   // 4100
    const int MROW  = BQ * NSEQ;     // 4096

    for (int l = 0; l < NLAY; l++) {
        rfft2_kernel<<<BQ * DD / 2, 256>>>(ab1);

        conv_w(W1f + (size_t)l * DD * 2 * DD, wt, DD, 2 * DD);
        run_mma(ab1, wt, b1f + (size_t)l * 2 * DD, nullptr, ab2, MFREQ, DD, 2 * DD, 1, 1, 2);
        conv_w(W2f + (size_t)l * 2 * DD * DD, wt2, 2 * DD, DD);
        run_mma(ab2, wt2, b2f + (size_t)l * DD, go, nullptr, MFREQ, 2 * DD, DD, 0, 0, 2);

        irfft2_kernel<<<BQ * DD / 2, 256>>>();
        resid_ln_kernel<<<MROW, 256>>>(x, y, g1 + (size_t)l * DD, be1 + (size_t)l * DD, ab1);

        conv_w(Wf1 + (size_t)l * DD * 4 * DD, wt, DD, 4 * DD);
        run_mma(ab1, wt, bf1 + (size_t)l * 4 * DD, nullptr, ab2, MROW, DD, 4 * DD, 1, 1, 2);
        conv_w(Wf2 + (size_t)l * 4 * DD * DD, wt2, 4 * DD, DD);
        run_mma(ab2, wt2, bf2 + (size_t)l * DD, y, nullptr, MROW, 4 * DD, DD, 0, 0, 2);

        resid_ln_kernel<<<MROW, 256>>>(x, y, g2 + (size_t)l * DD, be2 + (size_t)l * DD, ab1);
    }

    // Head: out = x @ Wh + bh  — single hi term (error does not propagate further)
    conv_w(Wh, wt, DD, VV);
    run_mma(ab1, wt, bh, (float*)d_out, nullptr, MROW, DD, VV, 0, 0, 1);
}

// round 16
// speedup vs baseline: 1.0301x; 1.0301x over previous
#include <cuda_runtime.h>
#include <cuda_fp16.h>
#include <cstdint>
#include <math.h>

// Problem constants
#define BQ 2
#define NSEQ 2048
#define VV 32000
#define DD 1024
#define NLAY 4
#define NF 1025          // NSEQ/2 + 1

#define MPAD 4224

// MMA tiling: CTA 128x128, BK=64, warp tile 64x32 (2x4 warps), 3-stage pipeline
#define ROWH 72                   // padded row stride in halves (144 B)
#define STGH (128 * ROWH)
#define NSTG 3
#define SMEM_DYN (NSTG * 2 * STGH * 2)   // 110592 B

// ---------------------------------------------------------------------------
// Scratch. A stored as [M, 2K] fp16 (hi | lo). W stored as [N, K] fp16 hi only.
// Interior GEMMs run virtual K2=2K (Ah*Wh + Al*Wh). Head runs Kv=K (hi only).
// ---------------------------------------------------------------------------
__device__ float g_x [BQ * NSEQ * DD];
__device__ float g_y [BQ * NSEQ * DD];
__device__ float g_go[2 * BQ * NF * DD];                  // freq-MLP out re | im
__device__ float2 g_tw[NSEQ / 2];

__device__ __half g_ab1[(size_t)MPAD * 2 * DD];           // split A', K=1024 inputs
__device__ __half g_ab2[(size_t)MPAD * 2 * 4096];         // split A', wide K (<=4096)
__device__ __half g_wt [(size_t)VV * DD];                 // W' hi (N<=32000, K=1024)
__device__ __half g_wt2[(size_t)DD * 4096];               // W' hi (N=1024, K<=4096)

// ---------------------------------------------------------------------------
// Helpers
// ---------------------------------------------------------------------------
__device__ __forceinline__ uint32_t cvta_smem(const void* p) {
    uint32_t a;
    asm("{ .reg .u64 t; cvta.to.shared.u64 t, %1; cvt.u32.u64 %0, t; }" : "=r"(a) : "l"(p));
    return a;
}
__device__ __forceinline__ void cp16(uint32_t dst, const void* src) {
    asm volatile("cp.async.cg.shared.global [%0], [%1], 16;" :: "r"(dst), "l"(src));
}
__device__ __forceinline__ void ldm_x4(uint32_t* r, uint32_t addr) {
    asm volatile("ldmatrix.sync.aligned.m8n8.x4.shared.b16 {%0,%1,%2,%3}, [%4];"
                 : "=r"(r[0]), "=r"(r[1]), "=r"(r[2]), "=r"(r[3]) : "r"(addr));
}
__device__ __forceinline__ void mma_fp16(float* c, const uint32_t* a, const uint32_t* b) {
    asm volatile(
        "mma.sync.aligned.m16n8k16.row.col.f32.f16.f16.f32 "
        "{%0,%1,%2,%3}, {%4,%5,%6,%7}, {%8,%9}, {%0,%1,%2,%3};"
        : "+f"(c[0]), "+f"(c[1]), "+f"(c[2]), "+f"(c[3])
        : "r"(a[0]), "r"(a[1]), "r"(a[2]), "r"(a[3]), "r"(b[0]), "r"(b[1]));
}

// split-store a pair of adjacent values: hi at +0, lo at +K (fp16)
__device__ __forceinline__ void split_store2(__half* p, int K, float a, float b) {
    __half ha = __float2half_rn(a), hb = __float2half_rn(b);
    __half la = __float2half_rn(a - __half2float(ha));
    __half lb = __float2half_rn(b - __half2float(hb));
    __half2 hh; hh.x = ha; hh.y = hb;
    __half2 ll; ll.x = la; ll.y = lb;
    *(__half2*)(p)     = hh;
    *(__half2*)(p + K) = ll;
}

__device__ __forceinline__ float gelu_exact(float v) {
    return 0.5f * v * (1.0f + erff(v * 0.70710678118654752f));
}

// ---------------------------------------------------------------------------
// Twiddles / embed
// ---------------------------------------------------------------------------
__global__ void twiddle_kernel() {
    int k = threadIdx.x;
    double ang = -2.0 * 3.14159265358979323846 * (double)k / (double)NSEQ;
    g_tw[k] = make_float2((float)cos(ang), (float)sin(ang));
}

__global__ void embed_kernel(const int* __restrict__ ids,
                             const float* __restrict__ emb,
                             const float* __restrict__ pos) {
    int t = blockIdx.x * blockDim.x + threadIdx.x;
    int bn = t >> 8;
    int d4 = (t & 255) << 2;
    int id = ids[bn];
    int n  = bn & (NSEQ - 1);
    float4 e = *(const float4*)(emb + (size_t)id * DD + d4);
    float4 p = *(const float4*)(pos + (size_t)n  * DD + d4);
    *(float4*)(g_x + (size_t)bn * DD + d4) =
        make_float4(e.x + p.x, e.y + p.y, e.z + p.z, e.w + p.w);
}

// ---------------------------------------------------------------------------
// FFT core. Bit-reversed DIT; first 3 stages (len 2/4/8) in registers
// (each thread owns 8 consecutive elements), remaining 8 stages in smem.
// ---------------------------------------------------------------------------
__device__ __forceinline__ int bitrev11(int i) { return (int)(__brev((unsigned)i) >> 21); }

template <bool INV>
__device__ __forceinline__ void bf(float2& u, float2& v, float2 w) {
    if (INV) w.y = -w.y;
    float vwx = v.x * w.x - v.y * w.y;
    float vwy = v.x * w.y + v.y * w.x;
    v = make_float2(u.x - vwx, u.y - vwy);
    u = make_float2(u.x + vwx, u.y + vwy);
}

template <bool INV>
__device__ __forceinline__ void fft_first3(float2* r) {
    float2 w0   = g_tw[0];
    float2 w256 = g_tw[256];
    float2 w512 = g_tw[512];
    float2 w768 = g_tw[768];
    // len = 2
    bf<INV>(r[0], r[1], w0); bf<INV>(r[2], r[3], w0);
    bf<INV>(r[4], r[5], w0); bf<INV>(r[6], r[7], w0);
    // len = 4
    bf<INV>(r[0], r[2], w0); bf<INV>(r[1], r[3], w512);
    bf<INV>(r[4], r[6], w0); bf<INV>(r[5], r[7], w512);
    // len = 8
    bf<INV>(r[0], r[4], w0);   bf<INV>(r[1], r[5], w256);
    bf<INV>(r[2], r[6], w512); bf<INV>(r[3], r[7], w768);
}

template <bool INV>
__device__ __forceinline__ void fft_rest(float2* s, int tid) {
    int hbits = 3;
    for (int len = 16; len <= NSEQ; len <<= 1, hbits++) {
        int half = len >> 1;
        int step = NSEQ >> (hbits + 1);
        for (int t = tid; t < NSEQ / 2; t += 256) {
            int j   = t & (half - 1);
            int idx = ((t >> hbits) << (hbits + 1)) + j;
            float2 w = g_tw[j * step];
            if (INV) w.y = -w.y;
            float2 u = s[idx];
            float2 v = s[idx + half];
            float vwx = v.x * w.x - v.y * w.y;
            float vwy = v.x * w.y + v.y * w.x;
            s[idx]        = make_float2(u.x + vwx, u.y + vwy);
            s[idx + half] = make_float2(u.x - vwx, u.y - vwy);
        }
        __syncthreads();
    }
}

// Forward: two real channels per complex FFT; writes split A' (row stride 2*DD)
__global__ void rfft2_kernel(__half* __restrict__ Os) {
    __shared__ float2 s[NSEQ];
    int tid = threadIdx.x;
    int b   = blockIdx.x >> 9;
    int d0  = (blockIdx.x & 511) << 1;
    const float* x0 = g_x + (size_t)b * NSEQ * DD + d0;

    int base = tid * 8;
    float2 r[8];
#pragma unroll
    for (int j = 0; j < 8; j++)
        r[j] = *(const float2*)(x0 + (size_t)bitrev11(base + j) * DD);
    fft_first3<false>(r);
#pragma unroll
    for (int j = 0; j < 8; j++) s[base + j] = r[j];
    __syncthreads();
    fft_rest<false>(s, tid);

    for (int k = tid; k < NF; k += 256) {
        float2 Z1 = s[k];
        float2 Z2 = s[(NSEQ - k) & (NSEQ - 1)];
        float re1 = 0.5f * (Z1.x + Z2.x), im1 = 0.5f * (Z1.y - Z2.y);
        float re2 = 0.5f * (Z1.y + Z2.y), im2 = 0.5f * (Z2.x - Z1.x);
        split_store2(Os + (size_t)(b * NF + k) * (2 * DD) + d0, DD, re1, re2);
        split_store2(Os + (size_t)((BQ + b) * NF + k) * (2 * DD) + d0, DD, im1, im2);
    }
}

// Inverse: two spectra from g_go -> one complex iFFT -> g_y
__global__ void irfft2_kernel() {
    __shared__ float2 s[NSEQ];
    __shared__ float2 G1[NF];
    __shared__ float2 G2[NF];
    int tid = threadIdx.x;
    int b   = blockIdx.x >> 9;
    int d0  = (blockIdx.x & 511) << 1;
    for (int k = tid; k < NF; k += 256) {
        float2 re = *(const float2*)(g_go + (size_t)(b * NF + k) * DD + d0);
        float2 im = *(const float2*)(g_go + (size_t)((BQ + b) * NF + k) * DD + d0);
        G1[k] = make_float2(re.x, im.x);
        G2[k] = make_float2(re.y, im.y);
    }
    __syncthreads();

    int base = tid * 8;
    float2 r[8];
#pragma unroll
    for (int j = 0; j < 8; j++) {
        int i = bitrev11(base + j);
        float2 z;
        if (i <= NSEQ / 2) {
            float2 a = G1[i], c = G2[i];
            z = make_float2(a.x - c.y, a.y + c.x);
        } else {
            float2 a = G1[NSEQ - i], c = G2[NSEQ - i];
            z = make_float2(a.x + c.y, c.x - a.y);
        }
        r[j] = z;
    }
    fft_first3<true>(r);
#pragma unroll
    for (int j = 0; j < 8; j++) s[base + j] = r[j];
    __syncthreads();
    fft_rest<true>(s, tid);

    float* out = g_y + (size_t)b * NSEQ * DD + d0;
    const float inv = 1.0f / (float)NSEQ;
    for (int i = tid; i < NSEQ; i += 256)
        *(float2*)(out + (size_t)i * DD) = make_float2(s[i].x * inv, s[i].y * inv);
}

// ---------------------------------------------------------------------------
// Weight conversion: W [K,N] fp32 -> W' [N,K] fp16 hi only
// ---------------------------------------------------------------------------
__global__ void convW_kernel(const float* __restrict__ W,
                             __half* __restrict__ O, int K, int N) {
    __shared__ float t[32][33];
    int n0 = blockIdx.x * 32, k0 = blockIdx.y * 32;
    int tx = threadIdx.x & 31, tr = threadIdx.x >> 5;
    for (int r = tr; r < 32; r += 8)
        t[r][tx] = W[(size_t)(k0 + r) * N + n0 + tx];
    __syncthreads();
    for (int r = tr; r < 32; r += 8) {
        float v = t[tx][r];
        O[(size_t)(n0 + r) * K + k0 + tx] = __float2half_rn(v);
    }
}

// ---------------------------------------------------------------------------
// HMMA GEMM over virtual Kv: A row stride Ka elements; W [N,Kw] wraps at Kw.
// Interior: Ka=2K, Kw=K, Kv=2K (Ah*Wh + Al*Wh). Head: Kv=K (hi only).
// CTA 128x128, BK=64, 3-stage cp.async, 256 threads, warp tile 64x32 (2x4).
// mode 0: fp32 out; mode 1: split out.
// ---------------------------------------------------------------------------
__global__ void __launch_bounds__(256, 2)
mma_kernel(const __half* __restrict__ Abf,
           const __half* __restrict__ Wt,
           const float* __restrict__ bias,
           float* __restrict__ C,
           __half* __restrict__ Cs,
           int M, int Nn, int Ka, int Kw, int Kv, int act, int mode) {
    extern __shared__ __half sm[];
    uint32_t smBase = cvta_smem(sm);

    int tid  = threadIdx.x;
    int bm   = blockIdx.x * 128;
    int bn   = blockIdx.y * 128;
    int wid  = tid >> 5, lane = tid & 31;
    int wm   = (wid >> 2) * 64;
    int wn   = (wid & 3) * 32;

    float c[4][4][4];
#pragma unroll
    for (int i = 0; i < 4; i++)
#pragma unroll
        for (int j = 0; j < 4; j++) {
            c[i][j][0] = 0.f; c[i][j][1] = 0.f; c[i][j][2] = 0.f; c[i][j][3] = 0.f;
        }

#define A_OFF(stg) (smBase + (uint32_t)(stg) * (2 * STGH * 2))
#define B_OFF(stg) (A_OFF(stg) + STGH * 2)

    // Per stage: A 128 rows x 8 chunks(16B) + B 128 rows x 8 chunks = 2048 chunks,
    // 8 per thread (256 threads).
#define LOAD_STAGE(stg, kt)                                                           \
    do {                                                                              \
        int k_  = (kt) << 6;                                                          \
        int kw_ = (k_ < Kw) ? k_ : k_ - Kw;                                           \
        _Pragma("unroll")                                                             \
        for (int i_ = 0; i_ < 8; i_++) {                                              \
            int ch_ = tid + (i_ << 8);                                                \
            if (ch_ < 1024) {                                                         \
                int row_ = ch_ >> 3, cc_ = (ch_ & 7) << 3;                            \
                cp16(A_OFF(stg) + (uint32_t)(row_ * ROWH + cc_) * 2,                  \
                     Abf + (size_t)(bm + row_) * Ka + k_ + cc_);                      \
            } else {                                                                  \
                int bh_ = ch_ - 1024;                                                 \
                int row_ = bh_ >> 3, cc_ = (bh_ & 7) << 3;                            \
                cp16(B_OFF(stg) + (uint32_t)(row_ * ROWH + cc_) * 2,                  \
                     Wt + (size_t)(bn + row_) * Kw + kw_ + cc_);                      \
            }                                                                         \
        }                                                                             \
    } while (0)

    int T = Kv >> 6;

#pragma unroll
    for (int p = 0; p < NSTG - 1; p++) {
        LOAD_STAGE(p, p);
        asm volatile("cp.async.commit_group;" ::: "memory");
    }

    for (int t = 0; t < T; t++) {
        asm volatile("cp.async.wait_group %0;" :: "n"(NSTG - 2) : "memory");
        __syncthreads();

        if (t + NSTG - 1 < T) {
            int st = (t + NSTG - 1) % NSTG;
            LOAD_STAGE(st, t + NSTG - 1);
        }
        asm volatile("cp.async.commit_group;" ::: "memory");

        int st = t % NSTG;
        uint32_t aB = A_OFF(st), bB = B_OFF(st);
#pragma unroll
        for (int ks = 0; ks < 4; ks++) {
            uint32_t a[4][4];
#pragma unroll
            for (int mt = 0; mt < 4; mt++) {
                int row = wm + mt * 16 + ((lane >> 3) & 1) * 8 + (lane & 7);
                int col = ks * 16 + (lane >> 4) * 8;
                ldm_x4(a[mt], aB + (uint32_t)(row * ROWH + col) * 2);
            }
            uint32_t b[4][2];
#pragma unroll
            for (int np = 0; np < 2; np++) {
                int nrow = wn + np * 16 + (lane >> 4) * 8 + (lane & 7);
                int col  = ks * 16 + ((lane >> 3) & 1) * 8;
                uint32_t r[4];
                ldm_x4(r, bB + (uint32_t)(nrow * ROWH + col) * 2);
                b[np * 2][0]     = r[0]; b[np * 2][1]     = r[1];
                b[np * 2 + 1][0] = r[2]; b[np * 2 + 1][1] = r[3];
            }
#pragma unroll
            for (int mt = 0; mt < 4; mt++)
#pragma unroll
                for (int nt = 0; nt < 4; nt++)
                    mma_fp16(c[mt][nt], a[mt], b[nt]);
        }
    }

    // epilogue
#pragma unroll
    for (int mt = 0; mt < 4; mt++) {
        int rowa = bm + wm + mt * 16 + (lane >> 2);
        int rowb = rowa + 8;
#pragma unroll
        for (int nt = 0; nt < 4; nt++) {
            int col = bn + wn + nt * 8 + (lane & 3) * 2;
            float b0 = bias[col], b1 = bias[col + 1];
            float v0 = c[mt][nt][0] + b0, v1 = c[mt][nt][1] + b1;
            float v2 = c[mt][nt][2] + b0, v3 = c[mt][nt][3] + b1;
            if (act) {
                v0 = gelu_exact(v0); v1 = gelu_exact(v1);
                v2 = gelu_exact(v2); v3 = gelu_exact(v3);
            }
            if (mode == 0) {
                if (rowa < M) *(float2*)(C + (size_t)rowa * Nn + col) = make_float2(v0, v1);
                if (rowb < M) *(float2*)(C + (size_t)rowb * Nn + col) = make_float2(v2, v3);
            } else {
                if (rowa < M) split_store2(Cs + (size_t)rowa * 2 * Nn + col, Nn, v0, v1);
                if (rowb < M) split_store2(Cs + (size_t)rowb * 2 * Nn + col, Nn, v2, v3);
            }
        }
    }
#undef A_OFF
#undef B_OFF
#undef LOAD_STAGE
}

// ---------------------------------------------------------------------------
// Fused residual add + LayerNorm; writes fp32 x and split fp16 x' (stride 2*DD)
// ---------------------------------------------------------------------------
__global__ void resid_ln_kernel(float* __restrict__ x,
                                const float* __restrict__ y,
                                const float* __restrict__ g,
                                const float* __restrict__ be,
                                __half* __restrict__ xs) {
    __shared__ float red[256];
    int tid = threadIdx.x;
    size_t base = (size_t)blockIdx.x * DD;

    float v[4];
#pragma unroll
    for (int i = 0; i < 4; i++) {
        int d = tid + i * 256;
        v[i] = x[base + d] + y[base + d];
    }
    float s = v[0] + v[1] + v[2] + v[3];
    red[tid] = s;
    __syncthreads();
    for (int o = 128; o > 0; o >>= 1) {
        if (tid < o) red[tid] += red[tid + o];
        __syncthreads();
    }
    float mean = red[0] * (1.0f / DD);
    __syncthreads();

    float sq = 0.0f;
#pragma unroll
    for (int i = 0; i < 4; i++) { float t = v[i] - mean; sq += t * t; }
    red[tid] = sq;
    __syncthreads();
    for (int o = 128; o > 0; o >>= 1) {
        if (tid < o) red[tid] += red[tid + o];
        __syncthreads();
    }
    float var = red[0] * (1.0f / DD);
    float r = rsqrtf(var + 1e-5f);

    __half* xrow = xs + (size_t)blockIdx.x * 2 * DD;
#pragma unroll
    for (int i = 0; i < 4; i++) {
        int d = tid + i * 256;
        float o = (v[i] - mean) * r * g[d] + be[d];
        x[base + d] = o;
        __half h = __float2half_rn(o);
        __half l = __float2half_rn(o - __half2float(h));
        xrow[d]      = h;
        xrow[d + DD] = l;
    }
}

// ---------------------------------------------------------------------------
// Launcher
// ---------------------------------------------------------------------------
static float* sym(const void* s) {
    void* p = nullptr;
    cudaGetSymbolAddress(&p, s);
    return (float*)p;
}

static void conv_w(const float* W, __half* wt, int K, int N) {
    convW_kernel<<<dim3(N / 32, K / 32), 256>>>(W, wt, K, N);
}

// terms: 2 = Ah*Wh + Al*Wh ; 1 = Ah*Wh only (head)
static void run_mma(const __half* Abf, const __half* wt, const float* bias,
                    float* C, __half* Cs, int M, int K, int N, int act, int mode,
                    int terms) {
    mma_kernel<<<dim3((M + 127) / 128, N / 128), 256, SMEM_DYN>>>(
        Abf, wt, bias, C, Cs, M, N, 2 * K, K, terms * K, act, mode);
}

extern "C" void kernel_launch(void* const* d_in, const int* in_sizes, int n_in,
                              void* d_out, int out_size) {
    const int*   ids  = (const int*)  d_in[0];
    const float* emb  = (const float*)d_in[1];
    const float* pos  = (const float*)d_in[2];
    const float* W1f  = (const float*)d_in[3];
    const float* b1f  = (const float*)d_in[4];
    const float* W2f  = (const float*)d_in[5];
    const float* b2f  = (const float*)d_in[6];
    const float* g1   = (const float*)d_in[7];
    const float* be1  = (const float*)d_in[8];
    const float* Wf1  = (const float*)d_in[9];
    const float* bf1  = (const float*)d_in[10];
    const float* Wf2  = (const float*)d_in[11];
    const float* bf2  = (const float*)d_in[12];
    const float* g2   = (const float*)d_in[13];
    const float* be2  = (const float*)d_in[14];
    const float* Wh   = (const float*)d_in[15];
    const float* bh   = (const float*)d_in[16];

    float* x  = sym(g_x);
    float* y  = sym(g_y);
    float* go = sym(g_go);
    __half* ab1 = (__half*)sym(g_ab1);
    __half* ab2 = (__half*)sym(g_ab2);
    __half* wt  = (__half*)sym(g_wt);
    __half* wt2 = (__half*)sym(g_wt2);

    cudaFuncSetAttribute(mma_kernel, cudaFuncAttributeMaxDynamicSharedMemorySize, SMEM_DYN);

    twiddle_kernel<<<1, 1024>>>();
    embed_kernel<<<(BQ * NSEQ * DD / 4) / 256, 256>>>(ids, emb, pos);

    const int MFREQ = 2 * BQ * NF;   // 4100
    const int MROW  = BQ * NSEQ;     // 4096

    for (int l = 0; l < NLAY; l++) {
        rfft2_kernel<<<BQ * DD / 2, 256>>>(ab1);

        conv_w(W1f + (size_t)l * DD * 2 * DD, wt, DD, 2 * DD);
        run_mma(ab1, wt, b1f + (size_t)l * 2 * DD, nullptr, ab2, MFREQ, DD, 2 * DD, 1, 1, 2);
        conv_w(W2f + (size_t)l * 2 * DD * DD, wt2, 2 * DD, DD);
        run_mma(ab2, wt2, b2f + (size_t)l * DD, go, nullptr, MFREQ, 2 * DD, DD, 0, 0, 2);

        irfft2_kernel<<<BQ * DD / 2, 256>>>();
        resid_ln_kernel<<<MROW, 256>>>(x, y, g1 + (size_t)l * DD, be1 + (size_t)l * DD, ab1);

        conv_w(Wf1 + (size_t)l * DD * 4 * DD, wt, DD, 4 * DD);
        run_mma(ab1, wt, bf1 + (size_t)l * 4 * DD, nullptr, ab2, MROW, DD, 4 * DD, 1, 1, 2);
        conv_w(Wf2 + (size_t)l * 4 * DD * DD, wt2, 4 * DD, DD);
        run_mma(ab2, wt2, bf2 + (size_t)l * DD, y, nullptr, MROW, 4 * DD, DD, 0, 0, 2);

        resid_ln_kernel<<<MROW, 256>>>(x, y, g2 + (size_t)l * DD, be2 + (size_t)l * DD, ab1);
    }

    // Head: out = x @ Wh + bh  — single hi term (error does not propagate further)
    conv_w(Wh, wt, DD, VV);
    run_mma(ab1, wt, bh, (float*)d_out, nullptr, MROW, DD, VV, 0, 0, 1);
}

// round 17
// speedup vs baseline: 1.0494x; 1.0187x over previous
#include <cuda_runtime.h>
#include <cuda_fp16.h>
#include <cstdint>
#include <math.h>

// Problem constants
#define BQ 2
#define NSEQ 2048
#define VV 32000
#define DD 1024
#define NLAY 4
#define NF 1025          // NSEQ/2 + 1

#define MPAD 4224

// MMA tiling: CTA 128x128, BK=64, warp tile 64x32 (2x4 warps), 3-stage pipeline
#define ROWH 72                   // padded row stride in halves (144 B)
#define STGH (128 * ROWH)
#define NSTG 3
#define SMEM_DYN (NSTG * 2 * STGH * 2)   // 110592 B

// ---------------------------------------------------------------------------
// Scratch. A stored as [M, 2K] fp16 (hi | lo). W stored as [N, K] fp16 hi only.
// ---------------------------------------------------------------------------
__device__ float g_x [BQ * NSEQ * DD];
__device__ float g_y [BQ * NSEQ * DD];
__device__ float g_go[2 * BQ * NF * DD];                  // freq-MLP out re | im
__device__ float2 g_tw[NSEQ / 2];

__device__ __half g_ab1[(size_t)MPAD * 2 * DD];
__device__ __half g_ab2[(size_t)MPAD * 2 * 4096];
__device__ __half g_wt [(size_t)VV * DD];
__device__ __half g_wt2[(size_t)DD * 4096];

// ---------------------------------------------------------------------------
// Helpers
// ---------------------------------------------------------------------------
__device__ __forceinline__ uint32_t cvta_smem(const void* p) {
    uint32_t a;
    asm("{ .reg .u64 t; cvta.to.shared.u64 t, %1; cvt.u32.u64 %0, t; }" : "=r"(a) : "l"(p));
    return a;
}
__device__ __forceinline__ void cp16(uint32_t dst, const void* src) {
    asm volatile("cp.async.cg.shared.global [%0], [%1], 16;" :: "r"(dst), "l"(src));
}
__device__ __forceinline__ void ldm_x4(uint32_t* r, uint32_t addr) {
    asm volatile("ldmatrix.sync.aligned.m8n8.x4.shared.b16 {%0,%1,%2,%3}, [%4];"
                 : "=r"(r[0]), "=r"(r[1]), "=r"(r[2]), "=r"(r[3]) : "r"(addr));
}
__device__ __forceinline__ void mma_fp16(float* c, const uint32_t* a, const uint32_t* b) {
    asm volatile(
        "mma.sync.aligned.m16n8k16.row.col.f32.f16.f16.f32 "
        "{%0,%1,%2,%3}, {%4,%5,%6,%7}, {%8,%9}, {%0,%1,%2,%3};"
        : "+f"(c[0]), "+f"(c[1]), "+f"(c[2]), "+f"(c[3])
        : "r"(a[0]), "r"(a[1]), "r"(a[2]), "r"(a[3]), "r"(b[0]), "r"(b[1]));
}

__device__ __forceinline__ void split_store2(__half* p, int K, float a, float b) {
    __half ha = __float2half_rn(a), hb = __float2half_rn(b);
    __half la = __float2half_rn(a - __half2float(ha));
    __half lb = __float2half_rn(b - __half2float(hb));
    __half2 hh; hh.x = ha; hh.y = hb;
    __half2 ll; ll.x = la; ll.y = lb;
    *(__half2*)(p)     = hh;
    *(__half2*)(p + K) = ll;
}

__device__ __forceinline__ float gelu_exact(float v) {
    return 0.5f * v * (1.0f + erff(v * 0.70710678118654752f));
}

// ---------------------------------------------------------------------------
// Twiddles / embed
// ---------------------------------------------------------------------------
__global__ void twiddle_kernel() {
    int k = threadIdx.x;
    double ang = -2.0 * 3.14159265358979323846 * (double)k / (double)NSEQ;
    g_tw[k] = make_float2((float)cos(ang), (float)sin(ang));
}

__global__ void embed_kernel(const int* __restrict__ ids,
                             const float* __restrict__ emb,
                             const float* __restrict__ pos) {
    int t = blockIdx.x * blockDim.x + threadIdx.x;
    int bn = t >> 8;
    int d4 = (t & 255) << 2;
    int id = ids[bn];
    int n  = bn & (NSEQ - 1);
    float4 e = *(const float4*)(emb + (size_t)id * DD + d4);
    float4 p = *(const float4*)(pos + (size_t)n  * DD + d4);
    *(float4*)(g_x + (size_t)bn * DD + d4) =
        make_float4(e.x + p.x, e.y + p.y, e.z + p.z, e.w + p.w);
}

// ---------------------------------------------------------------------------
// FFT core. Bit-reversed DIT; first 3 stages in registers (8 elems/thread),
// remaining 8 stages as 4 radix-4 smem passes (2 stages per pass).
// ---------------------------------------------------------------------------
__device__ __forceinline__ int bitrev11(int i) { return (int)(__brev((unsigned)i) >> 21); }

template <bool INV>
__device__ __forceinline__ void bf(float2& u, float2& v, float2 w) {
    if (INV) w.y = -w.y;
    float vwx = v.x * w.x - v.y * w.y;
    float vwy = v.x * w.y + v.y * w.x;
    v = make_float2(u.x - vwx, u.y - vwy);
    u = make_float2(u.x + vwx, u.y + vwy);
}

template <bool INV>
__device__ __forceinline__ void fft_first3(float2* r) {
    float2 w0   = g_tw[0];
    float2 w256 = g_tw[256];
    float2 w512 = g_tw[512];
    float2 w768 = g_tw[768];
    bf<INV>(r[0], r[1], w0); bf<INV>(r[2], r[3], w0);
    bf<INV>(r[4], r[5], w0); bf<INV>(r[6], r[7], w0);
    bf<INV>(r[0], r[2], w0); bf<INV>(r[1], r[3], w512);
    bf<INV>(r[4], r[6], w0); bf<INV>(r[5], r[7], w512);
    bf<INV>(r[0], r[4], w0);   bf<INV>(r[1], r[5], w256);
    bf<INV>(r[2], r[6], w512); bf<INV>(r[3], r[7], w768);
}

// stages len 16..2048 as radix-4 passes: L = 16, 64, 256, 1024 (stage pair L, 2L)
template <bool INV>
__device__ __forceinline__ void fft_rest4(float2* s, int tid) {
#pragma unroll
    for (int L = 16; L <= 1024; L <<= 2) {
        int q     = L >> 1;
        int stepL = NSEQ / L;
        int step2 = NSEQ / (2 * L);
        for (int t = tid; t < NSEQ / 4; t += 256) {
            int j    = t & (q - 1);
            int g    = t / q;
            int base = g * (L << 1) + j;
            float2 a0 = s[base];
            float2 a1 = s[base + q];
            float2 a2 = s[base + 2 * q];
            float2 a3 = s[base + 3 * q];
            float2 wL = g_tw[j * stepL];
            bf<INV>(a0, a1, wL);
            bf<INV>(a2, a3, wL);
            bf<INV>(a0, a2, g_tw[j * step2]);
            bf<INV>(a1, a3, g_tw[(j + q) * step2]);
            s[base]         = a0;
            s[base + q]     = a1;
            s[base + 2 * q] = a2;
            s[base + 3 * q] = a3;
        }
        __syncthreads();
    }
}

// Forward: two real channels per complex FFT; writes split A' (row stride 2*DD)
__global__ void rfft2_kernel(__half* __restrict__ Os) {
    __shared__ float2 s[NSEQ];
    int tid = threadIdx.x;
    int b   = blockIdx.x >> 9;
    int d0  = (blockIdx.x & 511) << 1;
    const float* x0 = g_x + (size_t)b * NSEQ * DD + d0;

    int base = tid * 8;
    float2 r[8];
#pragma unroll
    for (int j = 0; j < 8; j++)
        r[j] = *(const float2*)(x0 + (size_t)bitrev11(base + j) * DD);
    fft_first3<false>(r);
#pragma unroll
    for (int j = 0; j < 8; j++) s[base + j] = r[j];
    __syncthreads();
    fft_rest4<false>(s, tid);

    for (int k = tid; k < NF; k += 256) {
        float2 Z1 = s[k];
        float2 Z2 = s[(NSEQ - k) & (NSEQ - 1)];
        float re1 = 0.5f * (Z1.x + Z2.x), im1 = 0.5f * (Z1.y - Z2.y);
        float re2 = 0.5f * (Z1.y + Z2.y), im2 = 0.5f * (Z2.x - Z1.x);
        split_store2(Os + (size_t)(b * NF + k) * (2 * DD) + d0, DD, re1, re2);
        split_store2(Os + (size_t)((BQ + b) * NF + k) * (2 * DD) + d0, DD, im1, im2);
    }
}

// Inverse: two spectra from g_go -> one complex iFFT -> g_y
__global__ void irfft2_kernel() {
    __shared__ float2 s[NSEQ];
    __shared__ float2 G1[NF];
    __shared__ float2 G2[NF];
    int tid = threadIdx.x;
    int b   = blockIdx.x >> 9;
    int d0  = (blockIdx.x & 511) << 1;
    for (int k = tid; k < NF; k += 256) {
        float2 re = *(const float2*)(g_go + (size_t)(b * NF + k) * DD + d0);
        float2 im = *(const float2*)(g_go + (size_t)((BQ + b) * NF + k) * DD + d0);
        G1[k] = make_float2(re.x, im.x);
        G2[k] = make_float2(re.y, im.y);
    }
    __syncthreads();

    int base = tid * 8;
    float2 r[8];
#pragma unroll
    for (int j = 0; j < 8; j++) {
        int i = bitrev11(base + j);
        float2 z;
        if (i <= NSEQ / 2) {
            float2 a = G1[i], c = G2[i];
            z = make_float2(a.x - c.y, a.y + c.x);
        } else {
            float2 a = G1[NSEQ - i], c = G2[NSEQ - i];
            z = make_float2(a.x + c.y, c.x - a.y);
        }
        r[j] = z;
    }
    fft_first3<true>(r);
#pragma unroll
    for (int j = 0; j < 8; j++) s[base + j] = r[j];
    __syncthreads();
    fft_rest4<true>(s, tid);

    float* out = g_y + (size_t)b * NSEQ * DD + d0;
    const float inv = 1.0f / (float)NSEQ;
    for (int i = tid; i < NSEQ; i += 256)
        *(float2*)(out + (size_t)i * DD) = make_float2(s[i].x * inv, s[i].y * inv);
}

// ---------------------------------------------------------------------------
// Weight conversion: W [K,N] fp32 -> W' [N,K] fp16 hi only
// ---------------------------------------------------------------------------
__global__ void convW_kernel(const float* __restrict__ W,
                             __half* __restrict__ O, int K, int N) {
    __shared__ float t[32][33];
    int n0 = blockIdx.x * 32, k0 = blockIdx.y * 32;
    int tx = threadIdx.x & 31, tr = threadIdx.x >> 5;
    for (int r = tr; r < 32; r += 8)
        t[r][tx] = W[(size_t)(k0 + r) * N + n0 + tx];
    __syncthreads();
    for (int r = tr; r < 32; r += 8) {
        float v = t[tx][r];
        O[(size_t)(n0 + r) * K + k0 + tx] = __float2half_rn(v);
    }
}

// ---------------------------------------------------------------------------
// HMMA GEMM over virtual Kv: A row stride Ka elements; W [N,Kw] wraps at Kw.
// CTA 128x128, BK=64, 3-stage cp.async, 256 threads, warp tile 64x32 (2x4).
// ---------------------------------------------------------------------------
__global__ void __launch_bounds__(256, 2)
mma_kernel(const __half* __restrict__ Abf,
           const __half* __restrict__ Wt,
           const float* __restrict__ bias,
           float* __restrict__ C,
           __half* __restrict__ Cs,
           int M, int Nn, int Ka, int Kw, int Kv, int act, int mode) {
    extern __shared__ __half sm[];
    uint32_t smBase = cvta_smem(sm);

    int tid  = threadIdx.x;
    int bm   = blockIdx.x * 128;
    int bn   = blockIdx.y * 128;
    int wid  = tid >> 5, lane = tid & 31;
    int wm   = (wid >> 2) * 64;
    int wn   = (wid & 3) * 32;

    float c[4][4][4];
#pragma unroll
    for (int i = 0; i < 4; i++)
#pragma unroll
        for (int j = 0; j < 4; j++) {
            c[i][j][0] = 0.f; c[i][j][1] = 0.f; c[i][j][2] = 0.f; c[i][j][3] = 0.f;
        }

#define A_OFF(stg) (smBase + (uint32_t)(stg) * (2 * STGH * 2))
#define B_OFF(stg) (A_OFF(stg) + STGH * 2)

#define LOAD_STAGE(stg, kt)                                                           \
    do {                                                                              \
        int k_  = (kt) << 6;                                                          \
        int kw_ = (k_ < Kw) ? k_ : k_ - Kw;                                           \
        _Pragma("unroll")                                                             \
        for (int i_ = 0; i_ < 8; i_++) {                                              \
            int ch_ = tid + (i_ << 8);                                                \
            if (ch_ < 1024) {                                                         \
                int row_ = ch_ >> 3, cc_ = (ch_ & 7) << 3;                            \
                cp16(A_OFF(stg) + (uint32_t)(row_ * ROWH + cc_) * 2,                  \
                     Abf + (size_t)(bm + row_) * Ka + k_ + cc_);                      \
            } else {                                                                  \
                int bh_ = ch_ - 1024;                                                 \
                int row_ = bh_ >> 3, cc_ = (bh_ & 7) << 3;                            \
                cp16(B_OFF(stg) + (uint32_t)(row_ * ROWH + cc_) * 2,                  \
                     Wt + (size_t)(bn + row_) * Kw + kw_ + cc_);                      \
            }                                                                         \
        }                                                                             \
    } while (0)

    int T = Kv >> 6;

#pragma unroll
    for (int p = 0; p < NSTG - 1; p++) {
        LOAD_STAGE(p, p);
        asm volatile("cp.async.commit_group;" ::: "memory");
    }

    for (int t = 0; t < T; t++) {
        asm volatile("cp.async.wait_group %0;" :: "n"(NSTG - 2) : "memory");
        __syncthreads();

        if (t + NSTG - 1 < T) {
            int st = (t + NSTG - 1) % NSTG;
            LOAD_STAGE(st, t + NSTG - 1);
        }
        asm volatile("cp.async.commit_group;" ::: "memory");

        int st = t % NSTG;
        uint32_t aB = A_OFF(st), bB = B_OFF(st);
#pragma unroll
        for (int ks = 0; ks < 4; ks++) {
            uint32_t a[4][4];
#pragma unroll
            for (int mt = 0; mt < 4; mt++) {
                int row = wm + mt * 16 + ((lane >> 3) & 1) * 8 + (lane & 7);
                int col = ks * 16 + (lane >> 4) * 8;
                ldm_x4(a[mt], aB + (uint32_t)(row * ROWH + col) * 2);
            }
            uint32_t b[4][2];
#pragma unroll
            for (int np = 0; np < 2; np++) {
                int nrow = wn + np * 16 + (lane >> 4) * 8 + (lane & 7);
                int col  = ks * 16 + ((lane >> 3) & 1) * 8;
                uint32_t r[4];
                ldm_x4(r, bB + (uint32_t)(nrow * ROWH + col) * 2);
                b[np * 2][0]     = r[0]; b[np * 2][1]     = r[1];
                b[np * 2 + 1][0] = r[2]; b[np * 2 + 1][1] = r[3];
            }
#pragma unroll
            for (int mt = 0; mt < 4; mt++)
#pragma unroll
                for (int nt = 0; nt < 4; nt++)
                    mma_fp16(c[mt][nt], a[mt], b[nt]);
        }
    }

    // epilogue
#pragma unroll
    for (int mt = 0; mt < 4; mt++) {
        int rowa = bm + wm + mt * 16 + (lane >> 2);
        int rowb = rowa + 8;
#pragma unroll
        for (int nt = 0; nt < 4; nt++) {
            int col = bn + wn + nt * 8 + (lane & 3) * 2;
            float b0 = bias[col], b1 = bias[col + 1];
            float v0 = c[mt][nt][0] + b0, v1 = c[mt][nt][1] + b1;
            float v2 = c[mt][nt][2] + b0, v3 = c[mt][nt][3] + b1;
            if (act) {
                v0 = gelu_exact(v0); v1 = gelu_exact(v1);
                v2 = gelu_exact(v2); v3 = gelu_exact(v3);
            }
            if (mode == 0) {
                if (rowa < M) *(float2*)(C + (size_t)rowa * Nn + col) = make_float2(v0, v1);
                if (rowb < M) *(float2*)(C + (size_t)rowb * Nn + col) = make_float2(v2, v3);
            } else {
                if (rowa < M) split_store2(Cs + (size_t)rowa * 2 * Nn + col, Nn, v0, v1);
                if (rowb < M) split_store2(Cs + (size_t)rowb * 2 * Nn + col, Nn, v2, v3);
            }
        }
    }
#undef A_OFF
#undef B_OFF
#undef LOAD_STAGE
}

// ---------------------------------------------------------------------------
// Fused residual add + LayerNorm; shuffle reductions.
// Writes fp32 x and split fp16 x' (stride 2*DD)
// ---------------------------------------------------------------------------
__global__ void resid_ln_kernel(float* __restrict__ x,
                                const float* __restrict__ y,
                                const float* __restrict__ g,
                                const float* __restrict__ be,
                                __half* __restrict__ xs) {
    __shared__ float red[8];
    int tid  = threadIdx.x;
    int lane = tid & 31, wid = tid >> 5;
    size_t base = (size_t)blockIdx.x * DD;

    float v[4];
#pragma unroll
    for (int i = 0; i < 4; i++) {
        int d = tid + i * 256;
        v[i] = x[base + d] + y[base + d];
    }
    float s = v[0] + v[1] + v[2] + v[3];
#pragma unroll
    for (int o = 16; o > 0; o >>= 1) s += __shfl_xor_sync(0xffffffffu, s, o);
    if (lane == 0) red[wid] = s;
    __syncthreads();
    float mean = (red[0] + red[1] + red[2] + red[3] +
                  red[4] + red[5] + red[6] + red[7]) * (1.0f / DD);
    __syncthreads();

    float sq = 0.0f;
#pragma unroll
    for (int i = 0; i < 4; i++) { float t = v[i] - mean; sq += t * t; }
#pragma unroll
    for (int o = 16; o > 0; o >>= 1) sq += __shfl_xor_sync(0xffffffffu, sq, o);
    if (lane == 0) red[wid] = sq;
    __syncthreads();
    float var = (red[0] + red[1] + red[2] + red[3] +
                 red[4] + red[5] + red[6] + red[7]) * (1.0f / DD);
    float r = rsqrtf(var + 1e-5f);

    __half* xrow = xs + (size_t)blockIdx.x * 2 * DD;
#pragma unroll
    for (int i = 0; i < 4; i++) {
        int d = tid + i * 256;
        float o = (v[i] - mean) * r * g[d] + be[d];
        x[base + d] = o;
        __half h = __float2half_rn(o);
        __half l = __float2half_rn(o - __half2float(h));
        xrow[d]      = h;
        xrow[d + DD] = l;
    }
}

// ---------------------------------------------------------------------------
// Launcher
// ---------------------------------------------------------------------------
static float* sym(const void* s) {
    void* p = nullptr;
    cudaGetSymbolAddress(&p, s);
    return (float*)p;
}

static void conv_w(const float* W, __half* wt, int K, int N) {
    convW_kernel<<<dim3(N / 32, K / 32), 256>>>(W, wt, K, N);
}

// terms: 2 = Ah*Wh + Al*Wh ; 1 = Ah*Wh only (head)
static void run_mma(const __half* Abf, const __half* wt, const float* bias,
                    float* C, __half* Cs, int M, int K, int N, int act, int mode,
                    int terms) {
    mma_kernel<<<dim3((M + 127) / 128, N / 128), 256, SMEM_DYN>>>(
        Abf, wt, bias, C, Cs, M, N, 2 * K, K, terms * K, act, mode);
}

extern "C" void kernel_launch(void* const* d_in, const int* in_sizes, int n_in,
                              void* d_out, int out_size) {
    const int*   ids  = (const int*)  d_in[0];
    const float* emb  = (const float*)d_in[1];
    const float* pos  = (const float*)d_in[2];
    const float* W1f  = (const float*)d_in[3];
    const float* b1f  = (const float*)d_in[4];
    const float* W2f  = (const float*)d_in[5];
    const float* b2f  = (const float*)d_in[6];
    const float* g1   = (const float*)d_in[7];
    const float* be1  = (const float*)d_in[8];
    const float* Wf1  = (const float*)d_in[9];
    const float* bf1  = (const float*)d_in[10];
    const float* Wf2  = (const float*)d_in[11];
    const float* bf2  = (const float*)d_in[12];
    const float* g2   = (const float*)d_in[13];
    const float* be2  = (const float*)d_in[14];
    const float* Wh   = (const float*)d_in[15];
    const float* bh   = (const float*)d_in[16];

    float* x  = sym(g_x);
    float* y  = sym(g_y);
    float* go = sym(g_go);
    __half* ab1 = (__half*)sym(g_ab1);
    __half* ab2 = (__half*)sym(g_ab2);
    __half* wt  = (__half*)sym(g_wt);
    __half* wt2 = (__half*)sym(g_wt2);

    cudaFuncSetAttribute(mma_kernel, cudaFuncAttributeMaxDynamicSharedMemorySize, SMEM_DYN);

    twiddle_kernel<<<1, 1024>>>();
    embed_kernel<<<(BQ * NSEQ * DD / 4) / 256, 256>>>(ids, emb, pos);

    const int MFREQ = 2 * BQ * NF;   // 4100
    const int MROW  = BQ * NSEQ;     // 4096

    for (int l = 0; l < NLAY; l++) {
        rfft2_kernel<<<BQ * DD / 2, 256>>>(ab1);

        conv_w(W1f + (size_t)l * DD * 2 * DD, wt, DD, 2 * DD);
        run_mma(ab1, wt, b1f + (size_t)l * 2 * DD, nullptr, ab2, MFREQ, DD, 2 * DD, 1, 1, 2);
        conv_w(W2f + (size_t)l * 2 * DD * DD, wt2, 2 * DD, DD);
        run_mma(ab2, wt2, b2f + (size_t)l * DD, go, nullptr, MFREQ, 2 * DD, DD, 0, 0, 2);

        irfft2_kernel<<<BQ * DD / 2, 256>>>();
        resid_ln_kernel<<<MROW, 256>>>(x, y, g1 + (size_t)l * DD, be1 + (size_t)l * DD, ab1);

        conv_w(Wf1 + (size_t)l * DD * 4 * DD, wt, DD, 4 * DD);
        run_mma(ab1, wt, bf1 + (size_t)l * 4 * DD, nullptr, ab2, MROW, DD, 4 * DD, 1, 1, 2);
        conv_w(Wf2 + (size_t)l * 4 * DD * DD, wt2, 4 * DD, DD);
        run_mma(ab2, wt2, bf2 + (size_t)l * DD, y, nullptr, MROW, 4 * DD, DD, 0, 0, 2);

        resid_ln_kernel<<<MROW, 256>>>(x, y, g2 + (size_t)l * DD, be2 + (size_t)l * DD, ab1);
    }

    // Head: out = x @ Wh + bh  — single hi term (error does not propagate further)
    conv_w(Wh, wt, DD, VV);
    run_mma(ab1, wt, bh, (float*)d_out, nullptr, MROW, DD, VV, 0, 0, 1);
}